// round 1
// baseline (speedup 1.0000x reference)
#include <cuda_runtime.h>
#include <cuda_bf16.h>

#define BATCH 16
#define TDIM  1024
#define DDIM  1024
#define NTOP  5
#define RADIUS 15

// Per-output-group histogram of top-k index hits. out group g = t >> 6.
__device__ int g_counts[BATCH * DDIM];

// Map float bits to monotonically-increasing unsigned (total order).
__device__ __forceinline__ unsigned sortable(float f) {
    unsigned u = __float_as_uint(f);
    return (u & 0x80000000u) ? ~u : (u | 0x80000000u);
}

__global__ void zero_counts_kernel() {
    g_counts[blockIdx.x * DDIM + threadIdx.x] = 0;
}

// One warp per (b, t) row of 1024 floats. Each lane scans 32 elements (8x float4),
// keeps a local top-5 as packed keys, then the warp extracts the global top-5
// via 5 rounds of warp-max + pop, and atomically bumps the histogram.
__global__ void topk_hist_kernel(const float* __restrict__ in) {
    const unsigned FULL = 0xFFFFFFFFu;
    int warp = (blockIdx.x * blockDim.x + threadIdx.x) >> 5;   // row id, [0, 16384)
    int lane = threadIdx.x & 31;
    int t = warp & (TDIM - 1);
    int g = t >> 6;

    const float4* p = (const float4*)(in + (size_t)warp * DDIM);

    unsigned long long k0 = 0, k1 = 0, k2 = 0, k3 = 0, k4 = 0;

#pragma unroll
    for (int c = 0; c < 8; c++) {
        float4 v = p[lane + c * 32];
        int base = (lane + c * 32) * 4;
#pragma unroll
        for (int j = 0; j < 4; j++) {
            float f = (j == 0) ? v.x : (j == 1) ? v.y : (j == 2) ? v.z : v.w;
            // key: value-major, lowest-index-wins tiebreak (matches lax.top_k)
            unsigned long long key =
                ((unsigned long long)sortable(f) << 10) |
                (unsigned)(DDIM - 1 - (base + j));
            if (key > k4) {
                k4 = key;
                unsigned long long tmp;
                if (k4 > k3) { tmp = k3; k3 = k4; k4 = tmp; }
                if (k3 > k2) { tmp = k2; k2 = k3; k3 = tmp; }
                if (k2 > k1) { tmp = k1; k1 = k2; k2 = tmp; }
                if (k1 > k0) { tmp = k0; k0 = k1; k1 = tmp; }
            }
        }
    }

    // 5 rounds: find warp-wide max, owning lane pops its list, lane r records it.
#pragma unroll
    for (int r = 0; r < NTOP; r++) {
        unsigned long long cand = k0;
        unsigned long long best = cand;
#pragma unroll
        for (int off = 16; off; off >>= 1) {
            unsigned long long o = __shfl_xor_sync(FULL, best, off);
            if (o > best) best = o;
        }
        unsigned winners = __ballot_sync(FULL, cand == best);
        int winner = __ffs(winners) - 1;
        if (lane == winner) { k0 = k1; k1 = k2; k2 = k3; k3 = k4; k4 = 0; }
        if (lane == r) {
            int idx = (DDIM - 1) - (int)(best & 1023u);
            atomicAdd(&g_counts[g * DDIM + idx], 1);
        }
    }
}

// out[g][d] = sum_m counts[g][m] * NORM * exp(-0.125 * (d-m)^2), truncated at |d-m|<=15.
__global__ void conv_kernel(float* __restrict__ out) {
    __shared__ float cnt[DDIM];
    __shared__ float w[RADIUS + 1];
    int g = blockIdx.x;
    int d = threadIdx.x;

    if (d <= RADIUS) {
        // 1/(2*sqrt(2*pi))
        w[d] = 0.19947114020071635f * expf(-0.125f * (float)(d * d));
    }
    cnt[d] = (float)g_counts[g * DDIM + d];
    __syncthreads();

    float acc = 0.0f;
#pragma unroll
    for (int k = -RADIUS; k <= RADIUS; k++) {
        int m = d + k;
        if (m >= 0 && m < DDIM) {
            acc += cnt[m] * w[k < 0 ? -k : k];
        }
    }
    out[g * DDIM + d] = acc;
}

extern "C" void kernel_launch(void* const* d_in, const int* in_sizes, int n_in,
                              void* d_out, int out_size) {
    const float* in = (const float*)d_in[0];
    float* out = (float*)d_out;

    zero_counts_kernel<<<BATCH, DDIM>>>();
    // 16384 rows, 1 warp per row, 8 warps (256 threads) per block -> 2048 blocks
    topk_hist_kernel<<<2048, 256>>>(in);
    conv_kernel<<<BATCH, DDIM>>>(out);
}

// round 2
// speedup vs baseline: 1.5333x; 1.5333x over previous
#include <cuda_runtime.h>
#include <cuda_bf16.h>

#define BATCH  16
#define TDIM   1024
#define DDIM   1024
#define RADIUS 15

// Per-output-group histogram of top-5 index hits; g = t >> 6.
// Zero-initialized at module load; conv_kernel re-zeroes after reading,
// so the invariant (zero at entry of topk) holds on every call.
__device__ int g_counts[BATCH * DDIM];

// Monotone float->unsigned bit mapping (total order, matches float order on non-NaN).
__device__ __forceinline__ unsigned sortable(float f) {
    unsigned u = __float_as_uint(f);
    return u ^ (((unsigned)((int)u >> 31)) | 0x80000000u);
}
__device__ __forceinline__ float unsortable(unsigned s) {
    unsigned u = (s & 0x80000000u) ? (s ^ 0x80000000u) : ~s;
    return __uint_as_float(u);
}

// sortable(-inf): any finite float maps strictly above this.
#define SNEG_INF 0x007FFFFFu

// One warp per (b, t) row of 1024 floats. Warp-shared replicated top-5 list
// held as 64-bit keys: (sortable_value << 10) | (1023 - idx)  -> value-major,
// lowest-index-wins tie-break (matches lax.top_k).
__global__ void __launch_bounds__(256) topk_hist_kernel(const float* __restrict__ in) {
    const unsigned FULL = 0xFFFFFFFFu;
    int warp = (blockIdx.x * 256 + threadIdx.x) >> 5;   // row id [0, 16384)
    int lane = threadIdx.x & 31;
    int g = (warp & (TDIM - 1)) >> 6;

    const float4* p = (const float4*)(in + (size_t)warp * DDIM) + lane;

    unsigned long long k0, k1, k2, k3, k4;
    k0 = k1 = k2 = k3 = k4 = ((unsigned long long)SNEG_INF << 10);
    float t5f = __int_as_float(0xFF800000);  // -inf: current warp 5th-largest value

#pragma unroll
    for (int c = 0; c < 8; c++) {
        float4 v = p[c * 32];
        float m = fmaxf(fmaxf(v.x, v.y), fmaxf(v.z, v.w));
        // Fast path: skip unless some lane's best-of-4 reaches the warp threshold.
        if (__any_sync(FULL, m >= t5f)) {
#pragma unroll
            for (int j = 0; j < 4; j++) {
                float f = (j == 0) ? v.x : (j == 1) ? v.y : (j == 2) ? v.z : v.w;
                unsigned cand = sortable(f);
                // Iteratively extract warp-max candidates into the shared list.
                while (true) {
                    unsigned best = __reduce_max_sync(FULL, cand);
                    unsigned s4v = (unsigned)(k4 >> 10);
                    if (best < s4v) break;
                    // lowest lane == lowest element index for fixed (c, j)
                    int winner = __ffs(__ballot_sync(FULL, cand == best)) - 1;
                    int bidx = ((winner + c * 32) << 2) + j;
                    if (lane == winner) cand = 0;
                    unsigned long long key =
                        ((unsigned long long)best << 10) | (unsigned)(DDIM - 1 - bidx);
                    if (key > k4) {
                        if (key > k3) { k4 = k3;
                            if (key > k2) { k3 = k2;
                                if (key > k1) { k2 = k1;
                                    if (key > k0) { k1 = k0; k0 = key; }
                                    else k1 = key;
                                } else k2 = key;
                            } else k3 = key;
                        } else k4 = key;
                        t5f = unsortable((unsigned)(k4 >> 10));
                    }
                }
            }
        }
    }

    // List is replicated across lanes; lanes 0..4 each commit one entry.
    unsigned long long kk = k4;
    if (lane == 0) kk = k0;
    else if (lane == 1) kk = k1;
    else if (lane == 2) kk = k2;
    else if (lane == 3) kk = k3;
    if (lane < 5) {
        int idx = (DDIM - 1) - (int)(kk & 1023u);
        atomicAdd(&g_counts[g * DDIM + idx], 1);
    }
}

// out[g][d] = sum_m counts[g][m] * NORM * exp(-0.125*(d-m)^2), |d-m| <= 15.
// One block per g-row; zeroes its own row after the barrier (no cross-block halo,
// so this is race-free and restores the g_counts==0 invariant for the next call).
__global__ void conv_kernel(float* __restrict__ out) {
    __shared__ float cnt[DDIM + 2 * RADIUS];
    __shared__ float w[2 * RADIUS + 1];
    int g = blockIdx.x;
    int d = threadIdx.x;

    if (d < 2 * RADIUS + 1) {
        int k = d - RADIUS;
        w[d] = 0.19947114020071635f * expf(-0.125f * (float)(k * k));
    }
    cnt[d + RADIUS] = (float)g_counts[g * DDIM + d];
    if (d < RADIUS) { cnt[d] = 0.0f; cnt[DDIM + RADIUS + d] = 0.0f; }
    __syncthreads();

    g_counts[g * DDIM + d] = 0;   // restore invariant (after all reads in this block)

    float acc = 0.0f;
#pragma unroll
    for (int k = 0; k < 2 * RADIUS + 1; k++) {
        acc += cnt[d + k] * w[k];
    }
    out[g * DDIM + d] = acc;
}

extern "C" void kernel_launch(void* const* d_in, const int* in_sizes, int n_in,
                              void* d_out, int out_size) {
    const float* in = (const float*)d_in[0];
    float* out = (float*)d_out;

    // 16384 rows, 1 warp per row, 8 warps per block -> 2048 blocks
    topk_hist_kernel<<<2048, 256>>>(in);
    conv_kernel<<<BATCH, DDIM>>>(out);
}

// round 3
// speedup vs baseline: 2.5296x; 1.6497x over previous
#include <cuda_runtime.h>
#include <cuda_bf16.h>

#define BATCH  16
#define TDIM   1024
#define DDIM   1024
#define RADIUS 15

// Per-output-group histogram of top-5 index hits; g = t >> 6.
// Zero at module load; conv_kernel re-zeroes its own row after reading,
// so the invariant (zero at topk entry) holds on every graph replay.
__device__ int g_counts[BATCH * DDIM];

// Monotone float->unsigned bit mapping (order-preserving for non-NaN).
__device__ __forceinline__ unsigned sortable(float f) {
    unsigned u = __float_as_uint(f);
    return u ^ (((unsigned)((int)u >> 31)) | 0x80000000u);
}
__device__ __forceinline__ float unsortable(unsigned s) {
    unsigned u = (s & 0x80000000u) ? (s ^ 0x80000000u) : ~s;
    return __uint_as_float(u);
}

__device__ __forceinline__ float comp4(float4 v, int j) {
    return (j == 0) ? v.x : (j == 1) ? v.y : (j == 2) ? v.z : v.w;
}

// One warp per (b, t) row of 1024 floats.
// A: registers + branchless max trees.  B: tau = 5th-largest lane-max (REDUX knockout),
// provably <= row's 5th-largest value.  C: gather candidates >= tau (expected ~14/warp).
// D: 5 exact extraction rounds with (value, lowest-index) tie-break matching lax.top_k.
__global__ void __launch_bounds__(256) topk_hist_kernel(const float* __restrict__ in) {
    const unsigned FULL = 0xFFFFFFFFu;
    int warp = (blockIdx.x * 256 + threadIdx.x) >> 5;   // row id [0, 16384)
    int lane = threadIdx.x & 31;
    int g = (warp & (TDIM - 1)) >> 6;

    const float4* p = (const float4*)(in + (size_t)warp * DDIM) + lane;

    // ---- Phase A: load 32 elems/lane, group maxes (branchless) ----
    float4 v[8];
    float gmax[8];
#pragma unroll
    for (int c = 0; c < 8; c++) {
        v[c] = p[c * 32];
        gmax[c] = fmaxf(fmaxf(v[c].x, v[c].y), fmaxf(v[c].z, v[c].w));
    }
    float lmax = gmax[0];
#pragma unroll
    for (int c = 1; c < 8; c++) lmax = fmaxf(lmax, gmax[c]);

    // ---- Phase B: tau = 5th-largest of the 32 lane maxes ----
    unsigned s = sortable(lmax);
    unsigned tau_s = 0;
#pragma unroll
    for (int r = 0; r < 5; r++) {
        unsigned best = __reduce_max_sync(FULL, s);
        tau_s = best;
        int w = __ffs(__ballot_sync(FULL, s == best)) - 1;
        if (lane == w) s = 0;
    }
    float tauf = unsortable(tau_s);

    // ---- Phase C: collect candidates (value >= tau); keep per-lane best key + count ----
    // key = (sortable(value) << 10) | (1023 - idx): value-major, lowest-index-wins.
    unsigned long long ck = 0;
    int cnt = 0;
#pragma unroll
    for (int c = 0; c < 8; c++) {
        if (gmax[c] >= tauf) {
#pragma unroll
            for (int j = 0; j < 4; j++) {
                float f = comp4(v[c], j);
                if (f >= tauf) {
                    int idx = ((lane + c * 32) << 2) + j;
                    unsigned long long key =
                        ((unsigned long long)sortable(f) << 10) | (unsigned)(1023 - idx);
                    cnt++;
                    if (key > ck) ck = key;
                }
            }
        }
    }

    // ---- Phase D: extract exact top-5 of candidates ----
    int myidx = 0;
#pragma unroll
    for (int r = 0; r < 5; r++) {
        unsigned hi = (unsigned)(ck >> 10);                 // 0 when no candidate left
        unsigned bestv = __reduce_max_sync(FULL, hi);
        unsigned myinv = (unsigned)(ck & 1023u);
        unsigned inv_c = (hi == bestv) ? myinv : 0u;
        unsigned besti = __reduce_max_sync(FULL, inv_c);    // max inv == lowest idx
        if (lane == r) myidx = 1023 - (int)besti;
        if (hi == bestv && myinv == besti) {                // unique winner lane
            cnt--;
            if (cnt > 0) {
                unsigned long long ub = ck;                 // next best: key < ub
                unsigned long long nk = 0;
#pragma unroll
                for (int c = 0; c < 8; c++) {
                    if (gmax[c] >= tauf) {
#pragma unroll
                        for (int j = 0; j < 4; j++) {
                            float f = comp4(v[c], j);
                            if (f >= tauf) {
                                int idx = ((lane + c * 32) << 2) + j;
                                unsigned long long key =
                                    ((unsigned long long)sortable(f) << 10) |
                                    (unsigned)(1023 - idx);
                                if (key < ub && key > nk) nk = key;
                            }
                        }
                    }
                }
                ck = nk;
            } else {
                ck = 0;
            }
        }
    }

    if (lane < 5) atomicAdd(&g_counts[g * DDIM + myidx], 1);
}

// out[g][d] = sum_m counts[g][m] * NORM * exp(-0.125*(d-m)^2), |d-m| <= 15.
// One block per g-row (race-free self-zeroing: no cross-block halo).
__global__ void conv_kernel(float* __restrict__ out) {
    __shared__ float cnt[DDIM + 2 * RADIUS];
    __shared__ float w[2 * RADIUS + 1];
    int g = blockIdx.x;
    int d = threadIdx.x;

    if (d < 2 * RADIUS + 1) {
        int k = d - RADIUS;
        w[d] = 0.19947114020071635f * expf(-0.125f * (float)(k * k));
    }
    cnt[d + RADIUS] = (float)g_counts[g * DDIM + d];
    if (d < RADIUS) { cnt[d] = 0.0f; cnt[DDIM + RADIUS + d] = 0.0f; }
    __syncthreads();

    g_counts[g * DDIM + d] = 0;   // restore invariant (after all reads in this block)

    float acc = 0.0f;
#pragma unroll
    for (int k = 0; k < 2 * RADIUS + 1; k++) {
        acc += cnt[d + k] * w[k];
    }
    out[g * DDIM + d] = acc;
}

extern "C" void kernel_launch(void* const* d_in, const int* in_sizes, int n_in,
                              void* d_out, int out_size) {
    const float* in = (const float*)d_in[0];
    float* out = (float*)d_out;

    topk_hist_kernel<<<2048, 256>>>(in);   // 1 warp per row
    conv_kernel<<<BATCH, DDIM>>>(out);
}